// round 2
// baseline (speedup 1.0000x reference)
#include <cuda_runtime.h>

#define RAYS 16384
#define SAMP 64
#define NP (RAYS*SAMP)
#define GS 128
#define EE 16
#define HH 64
#define CIN 18

// Scratch (device globals; no allocation allowed)
__device__ float g_rgb[NP*3];
__device__ float g_sigma[NP];

// shared-memory float offsets (all 16B-aligned where float4-loaded)
#define OW1   0
#define OB1   1024
#define OW2   1088
#define OB2   5184
#define OW3   5248
#define OB3   6272
#define OCW1  6288
#define OCB1  7440
#define OCW2  7504
#define OCB2  11600
#define OCW3  11664
#define OCB3  11856
#define SMTOT 11860

#define FULLMASK 0xffffffffu

__device__ __forceinline__ float softplus100(float z) {
    float a = 100.0f * z;
    float sp = fmaxf(a, 0.0f) + __logf(1.0f + __expf(-fabsf(a)));
    return 0.01f * sp;
}

__global__ void __launch_bounds__(256)
points_kernel(const float* __restrict__ rays_o,
              const float* __restrict__ rays_d,
              const float* __restrict__ grid,
              const float* __restrict__ w1, const float* __restrict__ b1,
              const float* __restrict__ w2, const float* __restrict__ b2,
              const float* __restrict__ w3, const float* __restrict__ b3,
              const float* __restrict__ cw1, const float* __restrict__ cb1,
              const float* __restrict__ cw2, const float* __restrict__ cb2,
              const float* __restrict__ cw3, const float* __restrict__ cb3,
              const float* __restrict__ beta,
              const int* __restrict__ nearp,
              const int* __restrict__ farp,
              float* __restrict__ out)
{
    __shared__ __align__(16) float sm[SMTOT];
    {
        int tid = threadIdx.x;
        for (int t = tid; t < 1024; t += 256) sm[OW1 + t] = w1[t];
        for (int t = tid; t < 64;   t += 256) sm[OB1 + t] = b1[t];
        for (int t = tid; t < 4096; t += 256) sm[OW2 + t] = w2[t];
        for (int t = tid; t < 64;   t += 256) sm[OB2 + t] = b2[t];
        for (int t = tid; t < 1024; t += 256) sm[OW3 + t] = w3[t];
        for (int t = tid; t < 16;   t += 256) sm[OB3 + t] = b3[t];
        for (int t = tid; t < 1152; t += 256) sm[OCW1 + t] = cw1[t];
        for (int t = tid; t < 64;   t += 256) sm[OCB1 + t] = cb1[t];
        for (int t = tid; t < 4096; t += 256) sm[OCW2 + t] = cw2[t];
        for (int t = tid; t < 64;   t += 256) sm[OCB2 + t] = cb2[t];
        for (int t = tid; t < 192;  t += 256) sm[OCW3 + t] = cw3[t];
        for (int t = tid; t < 3;    t += 256) sm[OCB3 + t] = cb3[t];
    }
    __syncthreads();

    int gt   = blockIdx.x * 256 + threadIdx.x;  // 2 threads per point
    int p    = gt >> 1;
    int half = gt & 1;                          // lane pair partner via shfl_xor(.,1)
    int hb   = half * 32;                       // hidden-unit base owned by this thread
    int r    = p >> 6;
    int s    = p & 63;

    float nearf = (float)nearp[0];
    float farf  = (float)farp[0];
    float dt    = (farf - nearf) * (1.0f / (float)SAMP);
    float tmid  = nearf + ((float)s + 0.5f) * dt;

    // x = rays_o + t_mid * rays_d (no FMA contraction; keep floor() decisions
    // aligned with the reference)
    float xc[3];
    #pragma unroll
    for (int c = 0; c < 3; c++) {
        float o = rays_o[3*r + c];
        float d = rays_d[3*r + c];
        xc[c] = __fadd_rn(o, __fmul_rn(tmid, d));
    }

    int   i0[3];
    float f[3];
    bool  inb[3];
    #pragma unroll
    for (int c = 0; c < 3; c++) {
        float graw = __fmul_rn(__fmul_rn(__fadd_rn(__fdiv_rn(xc[c], 1.3f), 1.0f), 0.5f), 127.0f);
        inb[c] = (graw >= 0.0f) && (graw <= 127.0f);
        float gg = fminf(fmaxf(graw, 0.0f), 127.0f);
        int ii = (int)floorf(gg);
        if (ii > 126) ii = 126;
        i0[c] = ii;
        f[c] = gg - (float)ii;
    }
    bool mask = inb[0] && inb[1] && inb[2];

    float wx[2] = {1.0f - f[0], f[0]};
    float wy[2] = {1.0f - f[1], f[1]};
    float wz2[2] = {1.0f - f[2], f[2]};
    float wzh = wz2[half];                      // this thread handles corners with dz==half
    int base000 = (i0[0]*GS + i0[1])*GS + i0[2];

    // ---- trilinear gather (4 corners per thread) -> butterfly -> emb[16] ----
    float emb[EE];
    #pragma unroll
    for (int i = 0; i < EE; i++) emb[i] = 0.0f;
    #pragma unroll
    for (int c = 0; c < 4; c++) {
        const int dx = (c >> 1) & 1, dy = c & 1;
        const float w = wx[dx] * wy[dy] * wzh;
        const float4* cp = reinterpret_cast<const float4*>(
            grid + (size_t)(base000 + dx*(GS*GS) + dy*GS + half) * EE);
        #pragma unroll
        for (int q = 0; q < 4; q++) {
            float4 v = cp[q];
            emb[4*q+0] = fmaf(w, v.x, emb[4*q+0]);
            emb[4*q+1] = fmaf(w, v.y, emb[4*q+1]);
            emb[4*q+2] = fmaf(w, v.z, emb[4*q+2]);
            emb[4*q+3] = fmaf(w, v.w, emb[4*q+3]);
        }
    }
    #pragma unroll
    for (int i = 0; i < EE; i++) emb[i] += __shfl_xor_sync(FULLMASK, emb[i], 1);

    // ---- SDF layer1: 16 -> own 32 (no reduction needed; emb replicated) ----
    float h1o[32];
    #pragma unroll
    for (int jj = 0; jj < 32; jj++) {
        int j = hb + jj;
        float z = sm[OB1 + j];
        const float4* wr = reinterpret_cast<const float4*>(&sm[OW1 + j*EE]);
        #pragma unroll
        for (int q = 0; q < 4; q++) {
            float4 v = wr[q];
            z = fmaf(emb[4*q+0], v.x, z);
            z = fmaf(emb[4*q+1], v.y, z);
            z = fmaf(emb[4*q+2], v.z, z);
            z = fmaf(emb[4*q+3], v.w, z);
        }
        h1o[jj] = softplus100(z);
    }

    // ---- SDF layer2: 64 -> own 32 (partial over own 32 inputs + butterfly) ----
    float h2o[32];
    #pragma unroll
    for (int g = 0; g < 2; g++) {
        #pragma unroll
        for (int jj = 0; jj < 32; jj += 2) {
            float z0 = 0.0f, z1 = 0.0f;
            const float4* w0 = reinterpret_cast<const float4*>(&sm[OW2 + (32*g+jj+0)*HH + hb]);
            const float4* w1r = reinterpret_cast<const float4*>(&sm[OW2 + (32*g+jj+1)*HH + hb]);
            #pragma unroll
            for (int k4 = 0; k4 < 8; k4++) {
                float4 a = w0[k4];
                float4 bv = w1r[k4];
                z0 = fmaf(h1o[4*k4+0], a.x, z0);  z1 = fmaf(h1o[4*k4+0], bv.x, z1);
                z0 = fmaf(h1o[4*k4+1], a.y, z0);  z1 = fmaf(h1o[4*k4+1], bv.y, z1);
                z0 = fmaf(h1o[4*k4+2], a.z, z0);  z1 = fmaf(h1o[4*k4+2], bv.z, z1);
                z0 = fmaf(h1o[4*k4+3], a.w, z0);  z1 = fmaf(h1o[4*k4+3], bv.w, z1);
            }
            z0 += __shfl_xor_sync(FULLMASK, z0, 1);
            z1 += __shfl_xor_sync(FULLMASK, z1, 1);
            if (g == half) {
                h2o[jj+0] = softplus100(sm[OB2 + 32*g + jj + 0] + z0);
                h2o[jj+1] = softplus100(sm[OB2 + 32*g + jj + 1] + z1);
            }
        }
    }

    // ---- SDF layer3: own 32 -> 16 (butterfly; replicated result) ----
    float sdf = 0.0f;
    float cin[CIN];
    #pragma unroll
    for (int i = 0; i < EE; i++) {
        float z = 0.0f;
        const float4* wr = reinterpret_cast<const float4*>(&sm[OW3 + i*HH + hb]);
        #pragma unroll
        for (int k4 = 0; k4 < 8; k4++) {
            float4 v = wr[k4];
            z = fmaf(h2o[4*k4+0], v.x, z);
            z = fmaf(h2o[4*k4+1], v.y, z);
            z = fmaf(h2o[4*k4+2], v.z, z);
            z = fmaf(h2o[4*k4+3], v.w, z);
        }
        z += __shfl_xor_sync(FULLMASK, z, 1);
        z += sm[OB3 + i];
        if (i == 0) sdf = z; else cin[i-1] = z;
    }

    // ---- backward through SDF MLP: cotangent e0 on output ----
    // dz2_k = W3[0,k] * sigmoid(100*z2_k), sigmoid recovered as 1-exp(-100 h)
    #pragma unroll
    for (int kk = 0; kk < 32; kk++) {
        float sig2 = 1.0f - __expf(-100.0f * h2o[kk]);
        h2o[kk] = sm[OW3 + hb + kk] * sig2;       // h2o := dz2 (own 32)
    }
    // dz1_j = (sum_k dz2_k W2[k,j]) * sigmoid(100*z1_j)
    #pragma unroll
    for (int g = 0; g < 2; g++) {
        float pz[32];
        #pragma unroll
        for (int jj = 0; jj < 32; jj++) pz[jj] = 0.0f;
        #pragma unroll
        for (int kk = 0; kk < 32; kk++) {
            const float4* wr = reinterpret_cast<const float4*>(&sm[OW2 + (hb+kk)*HH + 32*g]);
            float d = h2o[kk];
            #pragma unroll
            for (int j4 = 0; j4 < 8; j4++) {
                float4 v = wr[j4];
                pz[4*j4+0] = fmaf(d, v.x, pz[4*j4+0]);
                pz[4*j4+1] = fmaf(d, v.y, pz[4*j4+1]);
                pz[4*j4+2] = fmaf(d, v.z, pz[4*j4+2]);
                pz[4*j4+3] = fmaf(d, v.w, pz[4*j4+3]);
            }
        }
        #pragma unroll
        for (int jj = 0; jj < 32; jj++) {
            float tot = pz[jj] + __shfl_xor_sync(FULLMASK, pz[jj], 1);
            if (g == half) {
                float sig1 = 1.0f - __expf(-100.0f * h1o[jj]);
                h1o[jj] = tot * sig1;             // h1o := dz1 (own 32)
            }
        }
    }
    // d_emb_i = sum_j dz1_j W1[j,i]  (partial over own 32 j + butterfly)
    float de[EE];
    #pragma unroll
    for (int i = 0; i < EE; i++) de[i] = 0.0f;
    #pragma unroll
    for (int jj = 0; jj < 32; jj++) {
        const float4* wr = reinterpret_cast<const float4*>(&sm[OW1 + (hb+jj)*EE]);
        float d = h1o[jj];
        #pragma unroll
        for (int q = 0; q < 4; q++) {
            float4 v = wr[q];
            de[4*q+0] = fmaf(d, v.x, de[4*q+0]);
            de[4*q+1] = fmaf(d, v.y, de[4*q+1]);
            de[4*q+2] = fmaf(d, v.z, de[4*q+2]);
            de[4*q+3] = fmaf(d, v.w, de[4*q+3]);
        }
    }
    #pragma unroll
    for (int i = 0; i < EE; i++) de[i] += __shfl_xor_sync(FULLMASK, de[i], 1);

    // ---- trilinear backward: re-gather own 4 corners, dot with d_emb ----
    float gx = 0.0f, gy = 0.0f, gz = 0.0f;
    #pragma unroll
    for (int c = 0; c < 4; c++) {
        const int dx = (c >> 1) & 1, dy = c & 1;
        const float4* cp = reinterpret_cast<const float4*>(
            grid + (size_t)(base000 + dx*(GS*GS) + dy*GS + half) * EE);
        float dot = 0.0f;
        #pragma unroll
        for (int q = 0; q < 4; q++) {
            float4 v = cp[q];
            dot = fmaf(de[4*q+0], v.x, dot);
            dot = fmaf(de[4*q+1], v.y, dot);
            dot = fmaf(de[4*q+2], v.z, dot);
            dot = fmaf(de[4*q+3], v.w, dot);
        }
        float sx = dx ? 1.0f : -1.0f;
        float sy = dy ? 1.0f : -1.0f;
        float sz = half ? 1.0f : -1.0f;
        gx = fmaf(sx * wy[dy] * wzh,   dot, gx);
        gy = fmaf(wx[dx] * sy * wzh,   dot, gy);
        gz = fmaf(wx[dx] * wy[dy] * sz, dot, gz);
    }
    gx += __shfl_xor_sync(FULLMASK, gx, 1);
    gy += __shfl_xor_sync(FULLMASK, gy, 1);
    gz += __shfl_xor_sync(FULLMASK, gz, 1);

    const float K = 48.846153846153847f;   // 0.5*(G-1)/BOUND
    float dX = gx * (inb[0] ? K : 0.0f);
    float dY = gy * (inb[1] ? K : 0.0f);
    float dZ = gz * (inb[2] ? K : 0.0f);

    if (half == 0) {
        out[RAYS*8 + 3*p + 0] = dX;
        out[RAYS*8 + 3*p + 1] = dY;
        out[RAYS*8 + 3*p + 2] = dZ;
    }

    float nn  = fmaxf(sqrtf(dX*dX + dY*dY + dZ*dZ), 1e-12f);
    float inv = 1.0f / nn;
    cin[15] = dX * inv;
    cin[16] = dY * inv;
    cin[17] = dZ * inv;

    // ---- color MLP layer1: 18 -> own 32 (ReLU) ----
    #pragma unroll
    for (int jj = 0; jj < 32; jj++) {
        int j = hb + jj;
        float z = sm[OCB1 + j];
        #pragma unroll
        for (int i = 0; i < CIN; i++) z = fmaf(cin[i], sm[OCW1 + j*CIN + i], z);
        h1o[jj] = fmaxf(z, 0.0f);
    }
    // ---- color layer2: 64 -> own 32 (ReLU) ----
    #pragma unroll
    for (int g = 0; g < 2; g++) {
        #pragma unroll
        for (int jj = 0; jj < 32; jj += 2) {
            float z0 = 0.0f, z1 = 0.0f;
            const float4* w0 = reinterpret_cast<const float4*>(&sm[OCW2 + (32*g+jj+0)*HH + hb]);
            const float4* w1r = reinterpret_cast<const float4*>(&sm[OCW2 + (32*g+jj+1)*HH + hb]);
            #pragma unroll
            for (int k4 = 0; k4 < 8; k4++) {
                float4 a = w0[k4];
                float4 bv = w1r[k4];
                z0 = fmaf(h1o[4*k4+0], a.x, z0);  z1 = fmaf(h1o[4*k4+0], bv.x, z1);
                z0 = fmaf(h1o[4*k4+1], a.y, z0);  z1 = fmaf(h1o[4*k4+1], bv.y, z1);
                z0 = fmaf(h1o[4*k4+2], a.z, z0);  z1 = fmaf(h1o[4*k4+2], bv.z, z1);
                z0 = fmaf(h1o[4*k4+3], a.w, z0);  z1 = fmaf(h1o[4*k4+3], bv.w, z1);
            }
            z0 += __shfl_xor_sync(FULLMASK, z0, 1);
            z1 += __shfl_xor_sync(FULLMASK, z1, 1);
            if (g == half) {
                h2o[jj+0] = fmaxf(sm[OCB2 + 32*g + jj + 0] + z0, 0.0f);
                h2o[jj+1] = fmaxf(sm[OCB2 + 32*g + jj + 1] + z1, 0.0f);
            }
        }
    }
    // ---- color layer3: own 32 -> 3 (sigmoid) ----
    #pragma unroll
    for (int i = 0; i < 3; i++) {
        float z = 0.0f;
        const float4* wr = reinterpret_cast<const float4*>(&sm[OCW3 + i*HH + hb]);
        #pragma unroll
        for (int k4 = 0; k4 < 8; k4++) {
            float4 v = wr[k4];
            z = fmaf(h2o[4*k4+0], v.x, z);
            z = fmaf(h2o[4*k4+1], v.y, z);
            z = fmaf(h2o[4*k4+2], v.z, z);
            z = fmaf(h2o[4*k4+3], v.w, z);
        }
        z += __shfl_xor_sync(FULLMASK, z, 1);
        z += sm[OCB3 + i];
        if (half == 0) g_rgb[3*p + i] = 1.0f / (1.0f + __expf(-z));
    }

    // ---- Laplace-CDF sigma (written by the odd lane) ----
    if (half == 1) {
        float be  = 0.015f + fabsf(beta[0]);
        float as  = fabsf(sdf);
        float em1 = __expf(-as / be) - 1.0f;
        float sgn = (sdf > 0.0f) ? 1.0f : ((sdf < 0.0f) ? -1.0f : 0.0f);
        float sg  = (0.5f + 0.5f * sgn * em1) / be;
        g_sigma[p] = mask ? sg : 0.0f;
    }
}

__global__ void __launch_bounds__(128)
render_kernel(const float* __restrict__ rays_d_norm,
              const int* __restrict__ nearp, const int* __restrict__ farp,
              float* __restrict__ out)
{
    int r = blockIdx.x * 128 + threadIdx.x;
    if (r >= RAYS) return;
    float nearf = (float)nearp[0];
    float farf  = (float)farp[0];
    float dt    = (farf - nearf) * (1.0f / (float)SAMP);
    const float* grads = out + RAYS*8;

    float cs = 0.0f;
    float aR = 0.f, aG = 0.f, aB = 0.f, aD = 0.f;
    float aN0 = 0.f, aN1 = 0.f, aN2 = 0.f, aA = 0.f;
    for (int s = 0; s < SAMP; s++) {
        int p = r * SAMP + s;
        float dd = g_sigma[p] * dt;
        float T  = __expf(-cs);          // exclusive prefix sum
        cs += dd;
        float w = (1.0f - __expf(-dd)) * T;
        aR = fmaf(w, g_rgb[3*p + 0], aR);
        aG = fmaf(w, g_rgb[3*p + 1], aG);
        aB = fmaf(w, g_rgb[3*p + 2], aB);
        float tm = nearf + ((float)s + 0.5f) * dt;
        aD = fmaf(w, tm, aD);
        float gx = grads[3*p + 0], gy = grads[3*p + 1], gz = grads[3*p + 2];
        float nn = fmaxf(sqrtf(gx*gx + gy*gy + gz*gz), 1e-12f);
        float wi = w / nn;
        aN0 = fmaf(wi, gx, aN0);
        aN1 = fmaf(wi, gy, aN1);
        aN2 = fmaf(wi, gz, aN2);
        aA += w;
    }
    float ir = 1.0f / rays_d_norm[r];
    out[8*r + 0] = aR;
    out[8*r + 1] = aG;
    out[8*r + 2] = aB;
    out[8*r + 3] = aD * ir;
    out[8*r + 4] = aN0;
    out[8*r + 5] = aN1;
    out[8*r + 6] = aN2;
    out[8*r + 7] = aA;
}

extern "C" void kernel_launch(void* const* d_in, const int* in_sizes, int n_in,
                              void* d_out, int out_size)
{
    const float* rays_o      = (const float*)d_in[0];
    const float* rays_d      = (const float*)d_in[1];
    const float* rays_d_norm = (const float*)d_in[2];
    const float* grid        = (const float*)d_in[3];
    const float* sw1 = (const float*)d_in[4];
    const float* sb1 = (const float*)d_in[5];
    const float* sw2 = (const float*)d_in[6];
    const float* sb2 = (const float*)d_in[7];
    const float* sw3 = (const float*)d_in[8];
    const float* sb3 = (const float*)d_in[9];
    const float* cw1 = (const float*)d_in[10];
    const float* cb1 = (const float*)d_in[11];
    const float* cw2 = (const float*)d_in[12];
    const float* cb2 = (const float*)d_in[13];
    const float* cw3 = (const float*)d_in[14];
    const float* cb3 = (const float*)d_in[15];
    const float* beta  = (const float*)d_in[16];
    const int*   nearp = (const int*)d_in[17];
    const int*   farp  = (const int*)d_in[18];
    float* out = (float*)d_out;

    points_kernel<<<(NP*2)/256, 256>>>(rays_o, rays_d, grid,
                                       sw1, sb1, sw2, sb2, sw3, sb3,
                                       cw1, cb1, cw2, cb2, cw3, cb3,
                                       beta, nearp, farp, out);
    render_kernel<<<RAYS/128, 128>>>(rays_d_norm, nearp, farp, out);
}